// round 6
// baseline (speedup 1.0000x reference)
#include <cuda_runtime.h>
#include <cuda_bf16.h>
#include <cstdint>

// SConv2dAvg as HMMA GEMM, double-buffered cross-chunk pipeline + ldmatrix.
// D[o,n] = sum_k W[o,k] P[k,n]; per CTA: n = 8 batches x 16 px = 128 cols,
// K=576 in 9 chunks of 64 (one (r,s) plane each, c contiguous).
// 3-product double-bf16 split: Whi*Phi + Whi*Plo + Wlo*Phi.

#define Y_DIM   63
#define COUT    64
#define KTOT    576
#define THREADS 256
// smem byte layout: A bufs [2][128 rows][144], B bufs [2][256 rows][144]
#define ABUF    18432
#define BBUF    36864
#define SMEM_TOTAL (2 * ABUF + 2 * BBUF)   // 110592

__device__ unsigned short g_Ahi[COUT * KTOT];
__device__ unsigned short g_Alo[COUT * KTOT];

__global__ void prep_A_kernel(const float* __restrict__ w) {
    int idx = blockIdx.x * 256 + threadIdx.x;
    if (idx >= COUT * KTOT) return;
    int o  = idx / KTOT;
    int kp = idx - o * KTOT;        // k' = rs*64 + c
    int rs = kp >> 6;
    int c  = kp & 63;
    float v = w[o * KTOT + c * 9 + rs];
    unsigned short hi;
    asm("cvt.rn.bf16.f32 %0, %1;" : "=h"(hi) : "f"(v));
    float rem = v - __uint_as_float(((unsigned)hi) << 16);
    unsigned short lo;
    asm("cvt.rn.bf16.f32 %0, %1;" : "=h"(lo) : "f"(rem));
    g_Ahi[idx] = hi;
    g_Alo[idx] = lo;
}

__device__ __forceinline__ uint32_t pack_bf16x2(float x, float y) {
    uint32_t r;
    asm("cvt.rn.satfinite.bf16x2.f32 %0, %2, %1;" : "=r"(r) : "f"(x), "f"(y));
    return r;
}

#define MMA(acc, a, b)                                                         \
    asm volatile("mma.sync.aligned.m16n8k16.row.col.f32.bf16.bf16.f32 "        \
        "{%0,%1,%2,%3}, {%4,%5,%6,%7}, {%8,%9}, {%0,%1,%2,%3};"                \
        : "+f"((acc)[0]), "+f"((acc)[1]), "+f"((acc)[2]), "+f"((acc)[3])       \
        : "r"((a)[0]), "r"((a)[1]), "r"((a)[2]), "r"((a)[3]),                  \
          "r"((b)[0]), "r"((b)[1]))

#define LDSM4(r, a)                                                            \
    asm volatile("ldmatrix.sync.aligned.m8n8.x4.shared.b16 {%0,%1,%2,%3}, [%4];" \
        : "=r"((r)[0]), "=r"((r)[1]), "=r"((r)[2]), "=r"((r)[3]) : "r"(a))
#define LDSM2(r, a)                                                            \
    asm volatile("ldmatrix.sync.aligned.m8n8.x2.shared.b16 {%0,%1}, [%2];"     \
        : "=r"((r)[0]), "=r"((r)[1]) : "r"(a))

// one k16 step: B frags via LDSM.x2, A frags via LDSM.x4, 24 MMAs
#define COMPUTE_KQ(kq) do {                                                    \
    uint32_t bh_[2][2], bl_[2][2];                                             \
    _Pragma("unroll") for (int nf = 0; nf < 2; nf++) {                         \
        uint32_t ba = sbBhi + boff0 + nf * 1152 + (kq) * 32;                   \
        LDSM2(bh_[nf], ba);                                                    \
        LDSM2(bl_[nf], ba + 18432);                                            \
    }                                                                          \
    _Pragma("unroll") for (int mf = 0; mf < 4; mf++) {                         \
        uint32_t ah_[4], al_[4];                                               \
        uint32_t aadr = sbA + aoff0 + mf * 2304 + (kq) * 32;                   \
        LDSM4(ah_, aadr);                                                      \
        LDSM4(al_, aadr + 9216);                                               \
        _Pragma("unroll") for (int nf = 0; nf < 2; nf++) {                     \
            MMA(acc[mf][nf], ah_, bh_[nf]);                                    \
            MMA(acc[mf][nf], ah_, bl_[nf]);                                    \
            MMA(acc[mf][nf], al_, bh_[nf]);                                    \
        }                                                                      \
    }                                                                          \
} while (0)

#define LDG_GRP(v, g)                                                          \
    _Pragma("unroll") for (int j = 0; j < 8; j++)                              \
        (v)[j] = __ldg(pp_ + (((h << 5) + (g) * 8 + j) << 14));

#define STS_GRP(v, g) do {                                                     \
    uint32_t hp[4], lp[4];                                                     \
    _Pragma("unroll") for (int q = 0; q < 4; q++) {                            \
        float a0 = (v)[2 * q], a1 = (v)[2 * q + 1];                            \
        hp[q] = pack_bf16x2(a0, a1);                                           \
        float r0 = a0 - __uint_as_float(hp[q] << 16);                          \
        float r1 = a1 - __uint_as_float(hp[q] & 0xFFFF0000u);                  \
        lp[q] = pack_bf16x2(r0, r1);                                           \
    }                                                                          \
    char* d_ = smem + bq_off + row * 144 + h * 64 + (g) * 16;                  \
    *(uint4*)d_ = make_uint4(hp[0], hp[1], hp[2], hp[3]);                      \
    *(uint4*)(d_ + 18432) = make_uint4(lp[0], lp[1], lp[2], lp[3]);            \
} while (0)

#define LDA(plN)                                                               \
    _Pragma("unroll") for (int i = 0; i < 4; i++) {                            \
        int e = tid + i * 256; int bsel = e >> 9; int e2 = e & 511;            \
        int m = e2 >> 3; int qq = e2 & 7;                                      \
        aa[i] = *(const uint4*)((const char*)(bsel ? g_Alo : g_Ahi)            \
                                + m * 1152 + (plN) * 128 + qq * 16);           \
    }

#define STA()                                                                  \
    _Pragma("unroll") for (int i = 0; i < 4; i++) {                            \
        int e = tid + i * 256; int bsel = e >> 9; int e2 = e & 511;            \
        int m = e2 >> 3; int qq = e2 & 7;                                      \
        *(uint4*)(smem + aq_off + (bsel * 64 + m) * 144 + qq * 16) = aa[i];    \
    }

__global__ __launch_bounds__(THREADS, 2) void sconv_hmma_kernel(
    const float* __restrict__ input,
    const float* __restrict__ bias,
    const int*   __restrict__ selh,
    const int*   __restrict__ selw,
    float*       __restrict__ out)
{
    extern __shared__ char smem[];
    const uint32_t sb = (uint32_t)__cvta_generic_to_shared(smem);

    const int tid  = threadIdx.x;
    const int lane = tid & 31;
    const int w    = tid >> 5;

    // grid: 63 y * 4 xt * 2 bh = 504
    const int bid = blockIdx.x;
    const int y   = bid >> 3;
    const int xt  = (bid & 7) >> 1;
    const int bh  = bid & 1;
    const int px0 = xt * 16;

    // gather mapping: thread owns B row = tid>>1, c-half h = tid&1
    const int row = tid >> 1;
    const int h   = tid & 1;
    const int b_local = row >> 4;
    const int pxl     = row & 15;
    const int pxc = min(px0 + pxl, Y_DIM - 1);
    const int sh  = selh[y * Y_DIM + pxc];
    const int sw  = selw[y * Y_DIM + pxc];
    const float* pbase = input + ((bh * 8 + b_local) << 20)
                       + (2 * y + sh) * 128 + 2 * pxc + sw;

    // fragment lane offsets
    const int a_lane_off = (lane & 15) * 144 + (lane & 16);
    const int b_lane_off = (lane & 7) * 144 + (lane & 8) * 2;
    const int aoff0 = a_lane_off;              // + mf*2304 + kq*32
    const int boff0 = w * 2304 + b_lane_off;   // + nf*1152 + kq*32

    float acc[4][2][4];
#pragma unroll
    for (int i = 0; i < 4; i++)
#pragma unroll
        for (int j = 0; j < 2; j++)
#pragma unroll
            for (int q = 0; q < 4; q++) acc[i][j][q] = 0.f;

    // ---- prologue: stage chunk 0 into buffers 0 ----
    {
        const float* pp_ = pbase;            // plane 0 (r=0,s=0)
        const int bq_off = 2 * ABUF;         // B buf 0
        const int aq_off = 0;                // A buf 0
        uint4 aa[4];
        LDA(0);
#pragma unroll
        for (int g = 0; g < 4; g++) {
            float v[8];
            LDG_GRP(v, g);
            STS_GRP(v, g);
        }
        STA();
    }
    __syncthreads();

    // ---- main loop: compute chunk ch from buf ch&1, gather ch+1 into buf ~ ----
    for (int ch = 0; ch < 9; ch++) {
        const int p = ch & 1;
        const uint32_t sbA   = sb + p * ABUF;
        const uint32_t sbBhi = sb + 2 * ABUF + p * BBUF;

        if (ch < 8) {
            const int plN   = ch + 1;
            const int pn    = plN & 1;
            const int bq_off = 2 * ABUF + pn * BBUF;
            const int aq_off = pn * ABUF;
            const float* pp_ = pbase + (plN / 3) * 128 + (plN - (plN / 3) * 3);

            float v0[8], v1[8], v2[8], v3[8];
            uint4 aa[4];
            LDG_GRP(v0, 0);
            LDG_GRP(v1, 1);
            LDA(plN);
            COMPUTE_KQ(0);
            LDG_GRP(v2, 2);
            COMPUTE_KQ(1);
            LDG_GRP(v3, 3);
            COMPUTE_KQ(2);
            STS_GRP(v0, 0);
            STA();
            COMPUTE_KQ(3);
            STS_GRP(v1, 1);
            STS_GRP(v2, 2);
            STS_GRP(v3, 3);
        } else {
            COMPUTE_KQ(0);
            COMPUTE_KQ(1);
            COMPUTE_KQ(2);
            COMPUTE_KQ(3);
        }
        __syncthreads();
    }

    // ---- epilogue: scalar stores (odd strides -> no vector alignment) ----
    const int fq = lane & 3;
    const int fr = lane >> 2;
    const int npx = min(16, Y_DIM - px0);
    const int ybase = y * Y_DIM + px0;

#pragma unroll
    for (int mf = 0; mf < 4; mf++) {
        const int o = mf * 16 + fr;
        const float bo0 = __ldg(bias + o);
        const float bo8 = __ldg(bias + o + 8);
#pragma unroll
        for (int nf = 0; nf < 2; nf++) {
            const int pp = nf * 8 + 2 * fq;            // px within tile
            const int b  = bh * 8 + w;                 // warp owns one batch
            long base0 = ((long)(b * COUT + o)) * (Y_DIM * Y_DIM) + ybase + pp;
            long base8 = base0 + 8L * (Y_DIM * Y_DIM);
            if (pp < npx) {
                out[base0] = acc[mf][nf][0] + bo0;
                out[base8] = acc[mf][nf][2] + bo8;
            }
            if (pp + 1 < npx) {
                out[base0 + 1] = acc[mf][nf][1] + bo0;
                out[base8 + 1] = acc[mf][nf][3] + bo8;
            }
        }
    }
}

extern "C" void kernel_launch(void* const* d_in, const int* in_sizes, int n_in,
                              void* d_out, int out_size)
{
    const float* input  = (const float*)d_in[0];
    const float* weight = (const float*)d_in[1];
    const float* bias   = (const float*)d_in[2];
    const int*   selh   = (const int*)d_in[3];
    const int*   selw   = (const int*)d_in[4];
    float*       out    = (float*)d_out;

    cudaFuncSetAttribute(sconv_hmma_kernel,
                         cudaFuncAttributeMaxDynamicSharedMemorySize, SMEM_TOTAL);

    prep_A_kernel<<<(COUT * KTOT + 255) / 256, 256>>>(weight);
    sconv_hmma_kernel<<<Y_DIM * 4 * 2, THREADS, SMEM_TOTAL>>>(input, bias, selh, selw, out);
}

// round 7
// speedup vs baseline: 1.0747x; 1.0747x over previous
#include <cuda_runtime.h>
#include <cuda_bf16.h>
#include <cstdint>

// SConv2dAvg as HMMA GEMM. Per CTA: n = 16 batches x 16 px = 256 cols,
// K=576 in 9 chunks of 64 (one (r,s) plane, c contiguous).
// 3-product double-bf16 split: Whi*Phi + Whi*Plo + Wlo*Phi.
// 512 threads, 16 warps, warp tile m32 x n32.

#define Y_DIM   63
#define COUT    64
#define KTOT    576
#define THREADS 512

// smem bytes: Ahi[64][144] Alo[64][144] Bhi[256][144] Blo[256][144]
#define AHI_OFF 0
#define ALO_OFF 9216
#define BHI_OFF 18432
#define BLO_OFF 55296
#define SMEM_TOTAL 92160

__device__ unsigned short g_Ahi[COUT * KTOT];
__device__ unsigned short g_Alo[COUT * KTOT];

__global__ void prep_A_kernel(const float* __restrict__ w) {
    int idx = blockIdx.x * 256 + threadIdx.x;
    if (idx >= COUT * KTOT) return;
    int o  = idx / KTOT;
    int kp = idx - o * KTOT;        // k' = rs*64 + c
    int rs = kp >> 6;
    int c  = kp & 63;
    float v = w[o * KTOT + c * 9 + rs];
    unsigned short hi;
    asm("cvt.rn.bf16.f32 %0, %1;" : "=h"(hi) : "f"(v));
    float rem = v - __uint_as_float(((unsigned)hi) << 16);
    unsigned short lo;
    asm("cvt.rn.bf16.f32 %0, %1;" : "=h"(lo) : "f"(rem));
    g_Ahi[idx] = hi;
    g_Alo[idx] = lo;
}

__device__ __forceinline__ uint32_t pack_bf16x2(float x, float y) {
    uint32_t r;
    asm("cvt.rn.satfinite.bf16x2.f32 %0, %2, %1;" : "=r"(r) : "f"(x), "f"(y));
    return r;
}

#define MMA(acc, a, b)                                                         \
    asm volatile("mma.sync.aligned.m16n8k16.row.col.f32.bf16.bf16.f32 "        \
        "{%0,%1,%2,%3}, {%4,%5,%6,%7}, {%8,%9}, {%0,%1,%2,%3};"                \
        : "+f"((acc)[0]), "+f"((acc)[1]), "+f"((acc)[2]), "+f"((acc)[3])       \
        : "r"((a)[0]), "r"((a)[1]), "r"((a)[2]), "r"((a)[3]),                  \
          "r"((b)[0]), "r"((b)[1]))

#define LDSM4(r, a)                                                            \
    asm volatile("ldmatrix.sync.aligned.m8n8.x4.shared.b16 {%0,%1,%2,%3}, [%4];" \
        : "=r"((r)[0]), "=r"((r)[1]), "=r"((r)[2]), "=r"((r)[3]) : "r"(a))
#define LDSM2(r, a)                                                            \
    asm volatile("ldmatrix.sync.aligned.m8n8.x2.shared.b16 {%0,%1}, [%2];"     \
        : "=r"((r)[0]), "=r"((r)[1]) : "r"(a))

__global__ __launch_bounds__(THREADS, 2) void sconv_hmma_kernel(
    const float* __restrict__ input,
    const float* __restrict__ bias,
    const int*   __restrict__ selh,
    const int*   __restrict__ selw,
    float*       __restrict__ out)
{
    extern __shared__ char smem[];
    const uint32_t sb = (uint32_t)__cvta_generic_to_shared(smem);

    const int tid  = threadIdx.x;
    const int lane = tid & 31;
    const int w    = tid >> 5;
    const int wn   = w & 7;         // n32 tile
    const int wm   = w >> 3;        // m32 tile

    const int y   = blockIdx.x >> 2;
    const int px0 = (blockIdx.x & 3) * 16;

    // ---- gather mapping: B row = tid>>1 (= b*16 + pxl), c-half h = tid&1 ----
    const int row = tid >> 1;
    const int h   = tid & 1;
    const int b   = row >> 4;
    const int pxl = row & 15;
    const int pxc = min(px0 + pxl, Y_DIM - 1);
    const int sh  = selh[y * Y_DIM + pxc];
    const int sw  = selw[y * Y_DIM + pxc];
    const float* pbase = input + (b << 20) + (2 * y + sh) * 128 + 2 * pxc + sw;

    // fragment lane addresses
    const uint32_t a_addr0 = sb + (wm * 32 + (lane & 15)) * 144 + (lane & 16);
    const uint32_t b_addr0 = sb + BHI_OFF + (wn * 32 + (lane & 7)) * 144 + (lane & 8) * 2;

    float acc[2][4][4];
#pragma unroll
    for (int i = 0; i < 2; i++)
#pragma unroll
        for (int j = 0; j < 4; j++)
#pragma unroll
            for (int q = 0; q < 4; q++) acc[i][j][q] = 0.f;

    for (int ch = 0; ch < 9; ch++) {
        __syncthreads();

        // ---- stage A chunk hi/lo: 1024 uint4 over 512 threads ----
#pragma unroll
        for (int i = 0; i < 2; i++) {
            int e    = tid + i * THREADS;
            int bsel = e >> 9;
            int e2   = e & 511;
            int m    = e2 >> 3;
            int q    = e2 & 7;
            *(uint4*)(smem + (bsel ? ALO_OFF : AHI_OFF) + m * 144 + q * 16) =
                *(const uint4*)((const char*)(bsel ? g_Alo : g_Ahi)
                                + m * (KTOT * 2) + ch * 128 + q * 16);
        }

        // ---- gather this thread's 32 c-values, split hi/lo, store ----
        const float* p = pbase + (ch / 3) * 128 + (ch - (ch / 3) * 3);
#pragma unroll
        for (int g = 0; g < 4; g++) {
            float v[8];
#pragma unroll
            for (int j = 0; j < 8; j++)
                v[j] = __ldg(p + (((h << 5) + g * 8 + j) << 14));
            uint32_t hp[4], lp[4];
#pragma unroll
            for (int q = 0; q < 4; q++) {
                float a0 = v[2 * q], a1 = v[2 * q + 1];
                hp[q] = pack_bf16x2(a0, a1);
                float r0 = a0 - __uint_as_float(hp[q] << 16);
                float r1 = a1 - __uint_as_float(hp[q] & 0xFFFF0000u);
                lp[q] = pack_bf16x2(r0, r1);
            }
            char* d = smem + BHI_OFF + row * 144 + h * 64 + g * 16;
            *(uint4*)d = make_uint4(hp[0], hp[1], hp[2], hp[3]);
            *(uint4*)(d + (BLO_OFF - BHI_OFF)) = make_uint4(lp[0], lp[1], lp[2], lp[3]);
        }
        __syncthreads();

        // ---- compute: 4 k16 steps ----
#pragma unroll
        for (int kq = 0; kq < 4; kq++) {
            uint32_t ah[2][4], al[2][4];
#pragma unroll
            for (int mf = 0; mf < 2; mf++) {
                uint32_t aa = a_addr0 + mf * (16 * 144) + kq * 32;
                LDSM4(ah[mf], aa);
                LDSM4(al[mf], aa + ALO_OFF);
            }
#pragma unroll
            for (int nf = 0; nf < 4; nf++) {
                uint32_t ba = b_addr0 + nf * (8 * 144) + kq * 32;
                uint32_t bh[2], bl[2];
                LDSM2(bh, ba);
                LDSM2(bl, ba + (BLO_OFF - BHI_OFF));
#pragma unroll
                for (int mf = 0; mf < 2; mf++) {
                    MMA(acc[mf][nf], ah[mf], bh);
                    MMA(acc[mf][nf], ah[mf], bl);
                    MMA(acc[mf][nf], al[mf], bh);
                }
            }
        }
    }

    // ---- epilogue: scalar stores (odd output strides) ----
    const int fq   = lane & 3;
    const int fr   = lane >> 2;
    const int npx  = min(16, Y_DIM - px0);
    const int ybase = y * Y_DIM + px0;

#pragma unroll
    for (int mf = 0; mf < 2; mf++) {
        const int o = wm * 32 + mf * 16 + fr;
        const float bo0 = __ldg(bias + o);
        const float bo8 = __ldg(bias + o + 8);
#pragma unroll
        for (int nf = 0; nf < 4; nf++) {
            int n    = wn * 32 + nf * 8 + 2 * fq;
            int bcol = n >> 4;
            int pp   = n & 15;
            long base0 = ((long)(bcol * COUT + o)) * (Y_DIM * Y_DIM) + ybase + pp;
            long base8 = base0 + 8L * (Y_DIM * Y_DIM);
            if (pp < npx) {
                out[base0] = acc[mf][nf][0] + bo0;
                out[base8] = acc[mf][nf][2] + bo8;
            }
            if (pp + 1 < npx) {
                out[base0 + 1] = acc[mf][nf][1] + bo0;
                out[base8 + 1] = acc[mf][nf][3] + bo8;
            }
        }
    }
}

extern "C" void kernel_launch(void* const* d_in, const int* in_sizes, int n_in,
                              void* d_out, int out_size)
{
    const float* input  = (const float*)d_in[0];
    const float* weight = (const float*)d_in[1];
    const float* bias   = (const float*)d_in[2];
    const int*   selh   = (const int*)d_in[3];
    const int*   selw   = (const int*)d_in[4];
    float*       out    = (float*)d_out;

    cudaFuncSetAttribute(sconv_hmma_kernel,
                         cudaFuncAttributeMaxDynamicSharedMemorySize, SMEM_TOTAL);

    prep_A_kernel<<<(COUT * KTOT + 255) / 256, 256>>>(weight);
    sconv_hmma_kernel<<<Y_DIM * 4, THREADS, SMEM_TOTAL>>>(input, bias, selh, selw, out);
}